// round 1
// baseline (speedup 1.0000x reference)
#include <cuda_runtime.h>

#define NB   16
#define NWAY 5
#define NS   130
#define NQ   25
#define NQQ  75
#define CF   640
#define KT   16

#define SROWS (NB*NWAY*NS)   // 10400
#define TROWS (NB*NQQ*NQ)    // 30000

__device__ float g_S[SROWS * CF];        // normalized support
__device__ float g_T[TROWS * CF];        // normalized query
__device__ float g_mmd_s[NB * NWAY];
__device__ float g_mmd_q[NB * NQQ];

// sum_a exp(-a*d2) for alphas 0.125*{1,2,4,8,16}; d2 = max(2-2*dot, 0)
__device__ __forceinline__ float multigauss(float dot) {
    float d2  = fmaxf(2.0f - 2.0f * dot, 0.0f);
    float u   = __expf(-0.125f * d2);
    float u2  = u * u;
    float u4  = u2 * u2;
    float u8  = u4 * u4;
    float u16 = u8 * u8;
    return u + u2 + u4 + u8 + u16;
}

__device__ __forceinline__ float block_sum_red(float v, float* sbuf, int nwarps) {
    int tid = threadIdx.x;
    int lane = tid & 31, wid = tid >> 5;
#pragma unroll
    for (int o = 16; o > 0; o >>= 1) v += __shfl_down_sync(0xffffffffu, v, o);
    if (lane == 0) sbuf[wid] = v;
    __syncthreads();
    if (tid == 0) {
        float t = 0.f;
        for (int w = 0; w < nwarps; w++) t += sbuf[w];
        sbuf[0] = t;
    }
    __syncthreads();
    return sbuf[0];
}

// ---------------------------------------------------------------------------
// zero the atomic accumulator for mmd_s
__global__ void zero_kernel() {
    int t = threadIdx.x;
    if (t < NB * NWAY) g_mmd_s[t] = 0.0f;
}

// ---------------------------------------------------------------------------
// normalize: one block per 640-float row; center over feature dim, then l2norm
__global__ __launch_bounds__(160) void norm_kernel(
    const float* __restrict__ sup, const float* __restrict__ qry) {
    __shared__ float sbuf[8];
    int row = blockIdx.x;
    const float* src;
    float* dst;
    if (row < SROWS) {
        src = sup + (size_t)row * CF;
        dst = g_S + (size_t)row * CF;
    } else {
        int r = row - SROWS;
        src = qry + (size_t)r * CF;
        dst = g_T + (size_t)r * CF;
    }
    int tid = threadIdx.x;
    int lane = tid & 31, wid = tid >> 5;

    float4 v = ((const float4*)src)[tid];
    float s = v.x + v.y + v.z + v.w;
#pragma unroll
    for (int o = 16; o > 0; o >>= 1) s += __shfl_down_sync(0xffffffffu, s, o);
    if (lane == 0) sbuf[wid] = s;
    __syncthreads();
    if (tid == 0) {
        float t = 0.f;
        for (int w = 0; w < 5; w++) t += sbuf[w];
        sbuf[6] = t;
    }
    __syncthreads();
    float mean = sbuf[6] * (1.0f / CF);
    v.x -= mean; v.y -= mean; v.z -= mean; v.w -= mean;

    float ss = v.x*v.x + v.y*v.y + v.z*v.z + v.w*v.w;
#pragma unroll
    for (int o = 16; o > 0; o >>= 1) ss += __shfl_down_sync(0xffffffffu, ss, o);
    __syncthreads();
    if (lane == 0) sbuf[wid] = ss;
    __syncthreads();
    if (tid == 0) {
        float t = 0.f;
        for (int w = 0; w < 5; w++) t += sbuf[w];
        sbuf[6] = t;
    }
    __syncthreads();
    float inv = rsqrtf(sbuf[6] + 1e-12f);
    v.x *= inv; v.y *= inv; v.z *= inv; v.w *= inv;
    ((float4*)dst)[tid] = v;
}

// ---------------------------------------------------------------------------
// support self-MMD term: grid = 80*5 (one column tile of 32 per block)
// block 256 = 32(tm) x 8(tn); microtile 5 rows x 4 cols per thread
__global__ __launch_bounds__(256) void mmd_s_kernel() {
    __shared__ float ss[KT][160];  // transposed k-chunk, rows 130..159 zero
    __shared__ float red[8];
    int bx = blockIdx.x;
    int bw = bx / 5, nt = bx % 5;
    const float* Sb = g_S + (size_t)bw * NS * CF;
    int tid = threadIdx.x;
    int tm = tid & 31, tn = tid >> 5;
    int j0 = nt * 32;

    float acc[5][4];
#pragma unroll
    for (int i = 0; i < 5; i++)
#pragma unroll
        for (int j = 0; j < 4; j++) acc[i][j] = 0.f;

    for (int kc = 0; kc < CF / KT; kc++) {
        __syncthreads();
        for (int idx = tid; idx < 160 * 4; idx += 256) {
            int r = idx >> 2, kq = idx & 3;
            float4 v = make_float4(0.f, 0.f, 0.f, 0.f);
            if (r < NS) v = *(const float4*)(Sb + r * CF + kc * KT + kq * 4);
            ss[kq*4+0][r] = v.x; ss[kq*4+1][r] = v.y;
            ss[kq*4+2][r] = v.z; ss[kq*4+3][r] = v.w;
        }
        __syncthreads();
#pragma unroll
        for (int kk = 0; kk < KT; kk++) {
            float a[5], b[4];
#pragma unroll
            for (int ii = 0; ii < 5; ii++) a[ii] = ss[kk][tm + 32*ii];
#pragma unroll
            for (int jj = 0; jj < 4; jj++) b[jj] = ss[kk][j0 + tn + 8*jj];
#pragma unroll
            for (int ii = 0; ii < 5; ii++)
#pragma unroll
                for (int jj = 0; jj < 4; jj++)
                    acc[ii][jj] = fmaf(a[ii], b[jj], acc[ii][jj]);
        }
    }

    float lsum = 0.f;
#pragma unroll
    for (int ii = 0; ii < 5; ii++) {
        int i = tm + 32*ii;
#pragma unroll
        for (int jj = 0; jj < 4; jj++) {
            int j = j0 + tn + 8*jj;
            if (i < NS && j < NS && i != j) lsum += multigauss(acc[ii][jj]);
        }
    }
    __syncthreads();
    float total = block_sum_red(lsum, red, 8);
    if (tid == 0) atomicAdd(&g_mmd_s[bw], total * (1.0f / (NS * (NS - 1))));
}

// ---------------------------------------------------------------------------
// query self-MMD term: grid = 1200 (one (b,q) per block)
// block 256 = 32(tm rows) x 8(tn); 4 adjacent cols per thread (float4 LDS)
__global__ __launch_bounds__(256) void mmd_q_kernel() {
    __shared__ float ts[KT][32];   // rows 25..31 zero
    __shared__ float red[8];
    int bq = blockIdx.x;
    const float* Tb = g_T + (size_t)bq * NQ * CF;
    int tid = threadIdx.x;
    int tm = tid & 31, tn = tid >> 5;

    float acc[4] = {0.f, 0.f, 0.f, 0.f};

    for (int kc = 0; kc < CF / KT; kc++) {
        __syncthreads();
        if (tid < 32 * 4) {
            int r = tid >> 2, kq = tid & 3;
            float4 v = make_float4(0.f, 0.f, 0.f, 0.f);
            if (r < NQ) v = *(const float4*)(Tb + r * CF + kc * KT + kq * 4);
            ts[kq*4+0][r] = v.x; ts[kq*4+1][r] = v.y;
            ts[kq*4+2][r] = v.z; ts[kq*4+3][r] = v.w;
        }
        __syncthreads();
#pragma unroll
        for (int kk = 0; kk < KT; kk++) {
            float a = ts[kk][tm];
            float4 b = ((float4*)&ts[kk][0])[tn];
            acc[0] = fmaf(a, b.x, acc[0]);
            acc[1] = fmaf(a, b.y, acc[1]);
            acc[2] = fmaf(a, b.z, acc[2]);
            acc[3] = fmaf(a, b.w, acc[3]);
        }
    }

    float lsum = 0.f;
    int i = tm;
#pragma unroll
    for (int jj = 0; jj < 4; jj++) {
        int j = tn * 4 + jj;
        if (i < NQ && j < NQ && i != j) lsum += multigauss(acc[jj]);
    }
    __syncthreads();
    float total = block_sum_red(lsum, red, 8);
    if (tid == 0) g_mmd_q[bq] = total * (1.0f / (NQ * (NQ - 1)));
}

// ---------------------------------------------------------------------------
// cross term + final combine: grid = 16*75*5 = 6000, block 160 = 32(tm) x 5(tn)
// microtile: 5 rows (stride 32) x 5 adjacent cols per thread
__global__ __launch_bounds__(160) void cross_kernel(float* __restrict__ out) {
    __shared__ float as_[KT][160];  // S chunk, rows 130..159 zero
    __shared__ float bs_[KT][28];   // T chunk (25 rows)
    __shared__ float red[8];
    int bx = blockIdx.x;
    int b = bx / (NQQ * NWAY);
    int rem = bx % (NQQ * NWAY);
    int q = rem / NWAY;
    int w = rem % NWAY;
    const float* Sb = g_S + (size_t)(b * NWAY + w) * NS * CF;
    const float* Tb = g_T + (size_t)(b * NQQ + q) * NQ * CF;
    int tid = threadIdx.x;
    int tm = tid & 31, tn = tid >> 5;  // tn 0..4

    float acc[5][5];
#pragma unroll
    for (int i = 0; i < 5; i++)
#pragma unroll
        for (int j = 0; j < 5; j++) acc[i][j] = 0.f;

    for (int kc = 0; kc < CF / KT; kc++) {
        __syncthreads();
#pragma unroll
        for (int it = 0; it < 4; it++) {
            int idx = tid + it * 160;
            int r = idx >> 2, kq = idx & 3;
            float4 v = make_float4(0.f, 0.f, 0.f, 0.f);
            if (r < NS) v = *(const float4*)(Sb + r * CF + kc * KT + kq * 4);
            as_[kq*4+0][r] = v.x; as_[kq*4+1][r] = v.y;
            as_[kq*4+2][r] = v.z; as_[kq*4+3][r] = v.w;
        }
        if (tid < NQ * 4) {
            int r = tid >> 2, kq = tid & 3;
            float4 v = *(const float4*)(Tb + r * CF + kc * KT + kq * 4);
            bs_[kq*4+0][r] = v.x; bs_[kq*4+1][r] = v.y;
            bs_[kq*4+2][r] = v.z; bs_[kq*4+3][r] = v.w;
        }
        __syncthreads();
#pragma unroll
        for (int kk = 0; kk < KT; kk++) {
            float a[5], bb[5];
#pragma unroll
            for (int ii = 0; ii < 5; ii++) a[ii] = as_[kk][tm + 32*ii];
#pragma unroll
            for (int jj = 0; jj < 5; jj++) bb[jj] = bs_[kk][tn * 5 + jj];
#pragma unroll
            for (int ii = 0; ii < 5; ii++)
#pragma unroll
                for (int jj = 0; jj < 5; jj++)
                    acc[ii][jj] = fmaf(a[ii], bb[jj], acc[ii][jj]);
        }
    }

    float lsum = 0.f;
#pragma unroll
    for (int ii = 0; ii < 5; ii++) {
        int i = tm + 32 * ii;
        if (i < NS) {
#pragma unroll
            for (int jj = 0; jj < 5; jj++) lsum += multigauss(acc[ii][jj]);
        }
    }
    __syncthreads();
    float total = block_sum_red(lsum, red, 5);
    if (tid == 0) {
        float mmd_qs = total * (1.0f / (NS * NQ));
        out[(b * NQQ + q) * NWAY + w] =
            g_mmd_s[b * NWAY + w] + g_mmd_q[b * NQQ + q] - 2.0f * mmd_qs;
    }
}

// ---------------------------------------------------------------------------
extern "C" void kernel_launch(void* const* d_in, const int* in_sizes, int n_in,
                              void* d_out, int out_size) {
    const float* sup = (const float*)d_in[0];   // [16,5,130,640]
    const float* qry = (const float*)d_in[1];   // [16,75,25,640]
    float* out = (float*)d_out;                 // [16,75,5]
    (void)in_sizes; (void)n_in; (void)out_size;

    zero_kernel<<<1, 128>>>();
    norm_kernel<<<SROWS + TROWS, 160>>>(sup, qry);
    mmd_s_kernel<<<NB * NWAY * 5, 256>>>();
    mmd_q_kernel<<<NB * NQQ, 256>>>();
    cross_kernel<<<NB * NQQ * NWAY, 160>>>(out);
}

// round 3
// speedup vs baseline: 2.1974x; 2.1974x over previous
#include <cuda_runtime.h>
#include <cuda_bf16.h>
#include <cstdint>

#define NB   16
#define NWAY 5
#define NS   130
#define NQ   25
#define NQQ  75
#define CF   640
#define SROWS (NB*NWAY*NS)   // 10400
#define TROWS (NB*NQQ*NQ)    // 30000
#define CHUNKS (CF/64)       // 10 chunks of 64 bf16
#define RB    144            // smem row stride bytes (64 bf16 + 8 pad)

__device__ __nv_bfloat16 g_Shi[SROWS*CF];
__device__ __nv_bfloat16 g_Slo[SROWS*CF];
__device__ __nv_bfloat16 g_Thi[TROWS*CF];
__device__ __nv_bfloat16 g_Tlo[TROWS*CF];
__device__ float g_ss_sum[NB*NWAY];       // raw offdiag sums
__device__ float g_mmd_q[NB*NQQ];         // scaled
__device__ float g_qs_sum[NB*NQQ*NWAY];   // raw sums

// ---------------------------------------------------------------------------
__device__ __forceinline__ uint32_t smem_u32(const void* p) {
    uint32_t a;
    asm("{ .reg .u64 t; cvta.to.shared.u64 t, %1; cvt.u32.u64 %0, t; }"
        : "=r"(a) : "l"(p));
    return a;
}

__device__ __forceinline__ void ldsm_x4(uint32_t* r, uint32_t addr) {
    asm volatile("ldmatrix.sync.aligned.m8n8.x4.shared.b16 {%0,%1,%2,%3}, [%4];"
                 : "=r"(r[0]), "=r"(r[1]), "=r"(r[2]), "=r"(r[3]) : "r"(addr));
}

__device__ __forceinline__ void mma4(float* c, const uint32_t* a,
                                     uint32_t b0, uint32_t b1) {
    asm volatile(
        "mma.sync.aligned.m16n8k16.row.col.f32.bf16.bf16.f32 "
        "{%0,%1,%2,%3}, {%4,%5,%6,%7}, {%8,%9}, {%0,%1,%2,%3};"
        : "+f"(c[0]), "+f"(c[1]), "+f"(c[2]), "+f"(c[3])
        : "r"(a[0]), "r"(a[1]), "r"(a[2]), "r"(a[3]), "r"(b0), "r"(b1));
}

__device__ __forceinline__ float multigauss(float dot) {
    float d2  = fmaxf(2.0f - 2.0f * dot, 0.0f);
    float u   = __expf(-0.125f * d2);
    float u2 = u*u, u4 = u2*u2, u8 = u4*u4, u16 = u8*u8;
    return u + u2 + u4 + u8 + u16;
}

// ---------------------------------------------------------------------------
__global__ void zero_kernel() {
    int t = blockIdx.x * blockDim.x + threadIdx.x;
    if (t < NB * NQQ * NWAY) g_qs_sum[t] = 0.f;
}

// normalize: center + l2norm, emit bf16 hi/lo split
__global__ __launch_bounds__(160) void norm_kernel(
    const float* __restrict__ sup, const float* __restrict__ qry) {
    __shared__ float sbuf[8];
    int row = blockIdx.x;
    const float* src;
    __nv_bfloat16 *dh, *dl;
    if (row < SROWS) {
        src = sup + (size_t)row * CF;
        dh = g_Shi + (size_t)row * CF; dl = g_Slo + (size_t)row * CF;
    } else {
        int r = row - SROWS;
        src = qry + (size_t)r * CF;
        dh = g_Thi + (size_t)r * CF; dl = g_Tlo + (size_t)r * CF;
    }
    int tid = threadIdx.x, lane = tid & 31, wid = tid >> 5;

    float4 v = ((const float4*)src)[tid];
    float s = v.x + v.y + v.z + v.w;
#pragma unroll
    for (int o = 16; o > 0; o >>= 1) s += __shfl_down_sync(0xffffffffu, s, o);
    if (lane == 0) sbuf[wid] = s;
    __syncthreads();
    if (tid == 0) { float t = 0.f; for (int w = 0; w < 5; w++) t += sbuf[w]; sbuf[6] = t; }
    __syncthreads();
    float mean = sbuf[6] * (1.0f / CF);
    v.x -= mean; v.y -= mean; v.z -= mean; v.w -= mean;

    float ss = v.x*v.x + v.y*v.y + v.z*v.z + v.w*v.w;
#pragma unroll
    for (int o = 16; o > 0; o >>= 1) ss += __shfl_down_sync(0xffffffffu, ss, o);
    __syncthreads();
    if (lane == 0) sbuf[wid] = ss;
    __syncthreads();
    if (tid == 0) { float t = 0.f; for (int w = 0; w < 5; w++) t += sbuf[w]; sbuf[6] = t; }
    __syncthreads();
    float inv = rsqrtf(sbuf[6] + 1e-12f);
    float vv[4] = {v.x * inv, v.y * inv, v.z * inv, v.w * inv};

    union { __nv_bfloat16 b[4]; uint2 u; } ph, pl;
#pragma unroll
    for (int k = 0; k < 4; k++) {
        ph.b[k] = __float2bfloat16(vv[k]);
        pl.b[k] = __float2bfloat16(vv[k] - __bfloat162float(ph.b[k]));
    }
    *reinterpret_cast<uint2*>(dh + tid * 4) = ph.u;
    *reinterpret_cast<uint2*>(dl + tid * 4) = pl.u;
}

// ---------------------------------------------------------------------------
// cross Gram: CTA tile 128(s) x 128(t); 8 warps 4x2, warp tile 32x64
#define X_AHI 0
#define X_ALO (128*RB)
#define X_BHI (2*128*RB)
#define X_BLO (3*128*RB)
#define X_SMEM (4*128*RB)   // 73728

__global__ __launch_bounds__(256, 2) void cross_mma() {
    extern __shared__ char smem[];
    __shared__ float tab[16];
    uint32_t sb = smem_u32(smem);
    int tid = threadIdx.x, lane = tid & 31, wid = tid >> 5;
    int wm = wid >> 1, wn = wid & 1;
    int gid = lane >> 2, tig = lane & 3;

    int bx = blockIdx.x;
    int nt_t = bx % 15;
    int mt_t = (bx / 15) % 6;
    int b    = bx / 90;

    int aValid = 650 - mt_t * 128; if (aValid > 128) aValid = 128;
    int bValid = 1875 - nt_t * 128; if (bValid > 128) bValid = 128;
    const char* Ahi = (const char*)(g_Shi + ((size_t)b * 650 + mt_t * 128) * CF);
    const char* Alo = (const char*)(g_Slo + ((size_t)b * 650 + mt_t * 128) * CF);
    const char* Bhi = (const char*)(g_Thi + ((size_t)b * 1875 + nt_t * 128) * CF);
    const char* Blo = (const char*)(g_Tlo + ((size_t)b * 1875 + nt_t * 128) * CF);

    if (tid < 16) tab[tid] = 0.f;

    float acc[2][8][4];
#pragma unroll
    for (int i = 0; i < 2; i++)
#pragma unroll
        for (int j = 0; j < 8; j++)
#pragma unroll
            for (int k = 0; k < 4; k++) acc[i][j][k] = 0.f;

    // per-thread ldmatrix address parts
    int lrow = lane & 15, lcol = (lane >> 4) << 4;

    for (int c = 0; c < CHUNKS; c++) {
        __syncthreads();
#pragma unroll
        for (int it = 0; it < 4; it++) {
            int idx = tid + it * 256;
            int row = idx >> 3, seg = idx & 7;
            size_t go = (size_t)row * (CF * 2) + c * 128 + seg * 16;
            int so = row * RB + seg * 16;
            uint4 vh = make_uint4(0,0,0,0), vl = vh;
            if (row < aValid) {
                vh = *(const uint4*)(Ahi + go);
                vl = *(const uint4*)(Alo + go);
            }
            *(uint4*)(smem + X_AHI + so) = vh;
            *(uint4*)(smem + X_ALO + so) = vl;
            vh = make_uint4(0,0,0,0); vl = vh;
            if (row < bValid) {
                vh = *(const uint4*)(Bhi + go);
                vl = *(const uint4*)(Blo + go);
            }
            *(uint4*)(smem + X_BHI + so) = vh;
            *(uint4*)(smem + X_BLO + so) = vl;
        }
        __syncthreads();

#pragma unroll
        for (int ks = 0; ks < 4; ks++) {
            uint32_t ahi[2][4], alo[2][4];
#pragma unroll
            for (int mt = 0; mt < 2; mt++) {
                int roff = (wm * 32 + mt * 16 + lrow) * RB + ks * 32 + lcol;
                ldsm_x4(ahi[mt], sb + X_AHI + roff);
                ldsm_x4(alo[mt], sb + X_ALO + roff);
            }
#pragma unroll
            for (int p = 0; p < 4; p++) {
                uint32_t bhi[4], blo[4];
                int roff = (wn * 64 + p * 16 + lrow) * RB + ks * 32 + lcol;
                ldsm_x4(bhi, sb + X_BHI + roff);
                ldsm_x4(blo, sb + X_BLO + roff);
#pragma unroll
                for (int mt = 0; mt < 2; mt++) {
                    mma4(acc[mt][p*2+0], ahi[mt], bhi[0], bhi[2]);
                    mma4(acc[mt][p*2+0], ahi[mt], blo[0], blo[2]);
                    mma4(acc[mt][p*2+0], alo[mt], bhi[0], bhi[2]);
                    mma4(acc[mt][p*2+1], ahi[mt], bhi[1], bhi[3]);
                    mma4(acc[mt][p*2+1], ahi[mt], blo[1], blo[3]);
                    mma4(acc[mt][p*2+1], alo[mt], bhi[1], bhi[3]);
                }
            }
        }
    }

    // epilogue: multigauss + (w,q)-bucketed reduction
    int qb = nt_t * 128;
    int q_base = qb / 25;
    int w_base = (mt_t * 128) / 130;
#pragma unroll
    for (int mt = 0; mt < 2; mt++)
#pragma unroll
    for (int rh = 0; rh < 2; rh++) {
        int row = wm * 32 + mt * 16 + rh * 8 + gid;
        int gs = mt_t * 128 + row;
        if (gs < 650) {
            int wrel = gs / 130 - w_base;
            float run = 0.f;
            int qprev = (qb + wn * 64 + tig * 2) / 25;
#pragma unroll
            for (int nt = 0; nt < 8; nt++)
#pragma unroll
            for (int e = 0; e < 2; e++) {
                int gt = qb + wn * 64 + nt * 8 + tig * 2 + e;
                int q = gt / 25;
                if (q != qprev) {
                    atomicAdd(&tab[wrel * 8 + (qprev - q_base)], run);
                    run = 0.f; qprev = q;
                }
                if (gt < 1875) run += multigauss(acc[mt][nt][rh * 2 + e]);
            }
            atomicAdd(&tab[wrel * 8 + (qprev - q_base)], run);
        }
    }
    __syncthreads();
    if (tid < 16) {
        float v = tab[tid];
        if (v != 0.f) {
            int q = q_base + (tid & 7);
            int w = w_base + (tid >> 3);
            if (q < NQQ && w < NWAY)
                atomicAdd(&g_qs_sum[(b * NQQ + q) * NWAY + w], v);
        }
    }
}

// ---------------------------------------------------------------------------
// query self Gram: one warp per (b,q); warp tile 32x32 (25x25 valid)
#define QW_BYTES (2 * 32 * RB)   // hi+lo per warp = 9216

__global__ __launch_bounds__(256) void kqq_mma() {
    extern __shared__ char smem[];
    uint32_t sb = smem_u32(smem);
    int tid = threadIdx.x, lane = tid & 31, wid = tid >> 5;
    int gid = lane >> 2, tig = lane & 3;
    int p = blockIdx.x * 8 + wid;
    int b = p / NQQ, qi = p % NQQ;

    char* whi = smem + wid * QW_BYTES;
    char* wlo = whi + 32 * RB;
    const char* Hi = (const char*)(g_Thi + ((size_t)b * 1875 + qi * 25) * CF);
    const char* Lo = (const char*)(g_Tlo + ((size_t)b * 1875 + qi * 25) * CF);

    // zero pad rows 25..31 once
    for (int idx = lane; idx < 7 * 9; idx += 32) {
        int r = 25 + idx / 9, sgo = (idx % 9) * 16;
        *(uint4*)(whi + r * RB + sgo) = make_uint4(0,0,0,0);
        *(uint4*)(wlo + r * RB + sgo) = make_uint4(0,0,0,0);
    }

    float acc[2][4][4];
#pragma unroll
    for (int i = 0; i < 2; i++)
#pragma unroll
        for (int j = 0; j < 4; j++)
#pragma unroll
            for (int k = 0; k < 4; k++) acc[i][j][k] = 0.f;

    int lrow = lane & 15, lcol = (lane >> 4) << 4;
    uint32_t whi_u = sb + (uint32_t)(whi - smem);
    uint32_t wlo_u = whi_u + 32 * RB;

    for (int c = 0; c < CHUNKS; c++) {
        __syncwarp();
        for (int idx = lane; idx < 200; idx += 32) {
            int row = idx >> 3, seg = idx & 7;
            size_t go = (size_t)row * (CF * 2) + c * 128 + seg * 16;
            int so = row * RB + seg * 16;
            *(uint4*)(whi + so) = *(const uint4*)(Hi + go);
            *(uint4*)(wlo + so) = *(const uint4*)(Lo + go);
        }
        __syncwarp();
#pragma unroll
        for (int ks = 0; ks < 4; ks++) {
            uint32_t ahi[2][4], alo[2][4];
#pragma unroll
            for (int mt = 0; mt < 2; mt++) {
                int roff = (mt * 16 + lrow) * RB + ks * 32 + lcol;
                ldsm_x4(ahi[mt], whi_u + roff);
                ldsm_x4(alo[mt], wlo_u + roff);
            }
#pragma unroll
            for (int pp = 0; pp < 2; pp++) {
                uint32_t bhi[4], blo[4];
                int roff = (pp * 16 + lrow) * RB + ks * 32 + lcol;
                ldsm_x4(bhi, whi_u + roff);
                ldsm_x4(blo, wlo_u + roff);
#pragma unroll
                for (int mt = 0; mt < 2; mt++) {
                    mma4(acc[mt][pp*2+0], ahi[mt], bhi[0], bhi[2]);
                    mma4(acc[mt][pp*2+0], ahi[mt], blo[0], blo[2]);
                    mma4(acc[mt][pp*2+0], alo[mt], bhi[0], bhi[2]);
                    mma4(acc[mt][pp*2+1], ahi[mt], bhi[1], bhi[3]);
                    mma4(acc[mt][pp*2+1], ahi[mt], blo[1], blo[3]);
                    mma4(acc[mt][pp*2+1], alo[mt], bhi[1], bhi[3]);
                }
            }
        }
    }

    float sum = 0.f;
#pragma unroll
    for (int mt = 0; mt < 2; mt++)
#pragma unroll
    for (int nt = 0; nt < 4; nt++)
#pragma unroll
    for (int rh = 0; rh < 2; rh++)
#pragma unroll
    for (int e = 0; e < 2; e++) {
        int row = mt * 16 + rh * 8 + gid;
        int col = nt * 8 + tig * 2 + e;
        if (row < NQ && col < NQ && row != col)
            sum += multigauss(acc[mt][nt][rh * 2 + e]);
    }
#pragma unroll
    for (int o = 16; o > 0; o >>= 1) sum += __shfl_down_sync(0xffffffffu, sum, o);
    if (lane == 0) g_mmd_q[p] = sum * (1.0f / (NQ * (NQ - 1)));
}

// ---------------------------------------------------------------------------
// support self Gram: one CTA per (b,w); 9 warps 3x3, warp tile 48x48
#define S_HI 0
#define S_LO (144*RB)
#define S_SMEM (2*144*RB)   // 41472

__global__ __launch_bounds__(288) void kss_mma() {
    extern __shared__ char smem[];
    __shared__ float red[9];
    uint32_t sb = smem_u32(smem);
    int tid = threadIdx.x, lane = tid & 31, wid = tid >> 5;
    int wm = wid / 3, wn = wid % 3;
    int gid = lane >> 2, tig = lane & 3;
    int b = blockIdx.x / NWAY, w = blockIdx.x % NWAY;

    const char* Hi = (const char*)(g_Shi + ((size_t)(b * NWAY + w) * NS) * CF);
    const char* Lo = (const char*)(g_Slo + ((size_t)(b * NWAY + w) * NS) * CF);

    // zero pad rows 130..143 once
    for (int idx = tid; idx < 14 * 9; idx += 288) {
        int r = 130 + idx / 9, sgo = (idx % 9) * 16;
        *(uint4*)(smem + S_HI + r * RB + sgo) = make_uint4(0,0,0,0);
        *(uint4*)(smem + S_LO + r * RB + sgo) = make_uint4(0,0,0,0);
    }

    float acc[3][6][4];
#pragma unroll
    for (int i = 0; i < 3; i++)
#pragma unroll
        for (int j = 0; j < 6; j++)
#pragma unroll
            for (int k = 0; k < 4; k++) acc[i][j][k] = 0.f;

    int lrow = lane & 15, lcol = (lane >> 4) << 4;

    for (int c = 0; c < CHUNKS; c++) {
        __syncthreads();
        for (int idx = tid; idx < 130 * 8; idx += 288) {
            int row = idx >> 3, seg = idx & 7;
            size_t go = (size_t)row * (CF * 2) + c * 128 + seg * 16;
            int so = row * RB + seg * 16;
            *(uint4*)(smem + S_HI + so) = *(const uint4*)(Hi + go);
            *(uint4*)(smem + S_LO + so) = *(const uint4*)(Lo + go);
        }
        __syncthreads();
#pragma unroll
        for (int ks = 0; ks < 4; ks++) {
            uint32_t ahi[3][4], alo[3][4];
#pragma unroll
            for (int mt = 0; mt < 3; mt++) {
                int roff = (wm * 48 + mt * 16 + lrow) * RB + ks * 32 + lcol;
                ldsm_x4(ahi[mt], sb + S_HI + roff);
                ldsm_x4(alo[mt], sb + S_LO + roff);
            }
#pragma unroll
            for (int p = 0; p < 3; p++) {
                uint32_t bhi[4], blo[4];
                int roff = (wn * 48 + p * 16 + lrow) * RB + ks * 32 + lcol;
                ldsm_x4(bhi, sb + S_HI + roff);
                ldsm_x4(blo, sb + S_LO + roff);
#pragma unroll
                for (int mt = 0; mt < 3; mt++) {
                    mma4(acc[mt][p*2+0], ahi[mt], bhi[0], bhi[2]);
                    mma4(acc[mt][p*2+0], ahi[mt], blo[0], blo[2]);
                    mma4(acc[mt][p*2+0], alo[mt], bhi[0], bhi[2]);
                    mma4(acc[mt][p*2+1], ahi[mt], bhi[1], bhi[3]);
                    mma4(acc[mt][p*2+1], ahi[mt], blo[1], blo[3]);
                    mma4(acc[mt][p*2+1], alo[mt], bhi[1], bhi[3]);
                }
            }
        }
    }

    float sum = 0.f;
#pragma unroll
    for (int mt = 0; mt < 3; mt++)
#pragma unroll
    for (int nt = 0; nt < 6; nt++)
#pragma unroll
    for (int rh = 0; rh < 2; rh++)
#pragma unroll
    for (int e = 0; e < 2; e++) {
        int row = wm * 48 + mt * 16 + rh * 8 + gid;
        int col = wn * 48 + nt * 8 + tig * 2 + e;
        if (row < NS && col < NS && row != col)
            sum += multigauss(acc[mt][nt][rh * 2 + e]);
    }
#pragma unroll
    for (int o = 16; o > 0; o >>= 1) sum += __shfl_down_sync(0xffffffffu, sum, o);
    if (lane == 0) red[wid] = sum;
    __syncthreads();
    if (tid == 0) {
        float t = 0.f;
        for (int i = 0; i < 9; i++) t += red[i];
        g_ss_sum[b * NWAY + w] = t;
    }
}

// ---------------------------------------------------------------------------
__global__ void combine_kernel(float* __restrict__ out) {
    int idx = blockIdx.x * blockDim.x + threadIdx.x;
    if (idx >= NB * NQQ * NWAY) return;
    int w = idx % NWAY;
    int bq = idx / NWAY;
    int b = bq / NQQ;
    out[idx] = g_ss_sum[b * NWAY + w] * (1.0f / (NS * (NS - 1)))
             + g_mmd_q[bq]
             - 2.0f * g_qs_sum[idx] * (1.0f / (NS * NQ));
}

// ---------------------------------------------------------------------------
extern "C" void kernel_launch(void* const* d_in, const int* in_sizes, int n_in,
                              void* d_out, int out_size) {
    const float* sup = (const float*)d_in[0];
    const float* qry = (const float*)d_in[1];
    float* out = (float*)d_out;
    (void)in_sizes; (void)n_in; (void)out_size;

    cudaFuncSetAttribute(cross_mma, cudaFuncAttributeMaxDynamicSharedMemorySize, X_SMEM);
    cudaFuncSetAttribute(kqq_mma, cudaFuncAttributeMaxDynamicSharedMemorySize, 8 * QW_BYTES);
    cudaFuncSetAttribute(kss_mma, cudaFuncAttributeMaxDynamicSharedMemorySize, S_SMEM);

    zero_kernel<<<24, 256>>>();
    norm_kernel<<<SROWS + TROWS, 160>>>(sup, qry);
    kss_mma<<<NB * NWAY, 288, S_SMEM>>>();
    kqq_mma<<<150, 256, 8 * QW_BYTES>>>();
    cross_mma<<<NB * 6 * 15, 256, X_SMEM>>>(   );
    combine_kernel<<<(NB * NQQ * NWAY + 127) / 128, 128>>>(out);
}

// round 4
// speedup vs baseline: 2.6996x; 1.2285x over previous
#include <cuda_runtime.h>
#include <cuda_bf16.h>
#include <cstdint>

#define NB   16
#define NWAY 5
#define NS   130
#define NQ   25
#define NQQ  75
#define CF   640
#define SROWS (NB*NWAY*NS)   // 10400
#define TROWS (NB*NQQ*NQ)    // 30000
#define CH    20             // k-chunks of 32 bf16 (64 B)
#define RB    80             // smem row stride bytes (64 + 16 pad)
#define ROWB  (CF*2)         // gmem row bytes = 1280

__device__ __nv_bfloat16 g_Shi[SROWS*CF];
__device__ __nv_bfloat16 g_Sps[SROWS*CF];
__device__ __nv_bfloat16 g_Thi[TROWS*CF];
__device__ __nv_bfloat16 g_Tps[TROWS*CF];
__device__ float g_ss_sum[NB*NWAY];
__device__ float g_mmd_q[NB*NQQ];
__device__ float g_qs_sum[NB*NQQ*NWAY];

// ---------------------------------------------------------------------------
__device__ __forceinline__ uint32_t smem_u32(const void* p) {
    uint32_t a;
    asm("{ .reg .u64 t; cvta.to.shared.u64 t, %1; cvt.u32.u64 %0, t; }"
        : "=r"(a) : "l"(p));
    return a;
}
__device__ __forceinline__ void ldsm_x4(uint32_t* r, uint32_t addr) {
    asm volatile("ldmatrix.sync.aligned.m8n8.x4.shared.b16 {%0,%1,%2,%3}, [%4];"
                 : "=r"(r[0]), "=r"(r[1]), "=r"(r[2]), "=r"(r[3]) : "r"(addr));
}
__device__ __forceinline__ void mma4(float* c, const uint32_t* a,
                                     uint32_t b0, uint32_t b1) {
    asm volatile(
        "mma.sync.aligned.m16n8k16.row.col.f32.bf16.bf16.f32 "
        "{%0,%1,%2,%3}, {%4,%5,%6,%7}, {%8,%9}, {%0,%1,%2,%3};"
        : "+f"(c[0]), "+f"(c[1]), "+f"(c[2]), "+f"(c[3])
        : "r"(a[0]), "r"(a[1]), "r"(a[2]), "r"(a[3]), "r"(b0), "r"(b1));
}
__device__ __forceinline__ void cp16(uint32_t dst, const void* src, int szp) {
    asm volatile("cp.async.cg.shared.global [%0], [%1], 16, %2;"
                 :: "r"(dst), "l"(src), "r"(szp));
}
#define CP_COMMIT() asm volatile("cp.async.commit_group;" ::: "memory")
#define CP_WAIT1()  asm volatile("cp.async.wait_group 1;" ::: "memory")
#define CP_WAIT0()  asm volatile("cp.async.wait_group 0;" ::: "memory")

// acc = hihi + PP/256 ; dot = acc*256/257 ; d2 = 2 - 2*dot
__device__ __forceinline__ float multigauss_acc(float acc) {
    float d2 = fmaxf(2.0f - 1.9922178988326848f * acc, 0.0f);
    float u  = __expf(-0.125f * d2);
    float u2 = u*u, u4 = u2*u2, u8 = u4*u4, u16 = u8*u8;
    return u + u2 + u4 + u8 + u16;
}

// ---------------------------------------------------------------------------
__global__ void zero_kernel() {
    int t = blockIdx.x * blockDim.x + threadIdx.x;
    if (t < NB * NQQ * NWAY) g_qs_sum[t] = 0.f;
}

// normalize (one-pass moments) + bf16 scaled-split emit
__global__ __launch_bounds__(160) void norm_kernel(
    const float* __restrict__ sup, const float* __restrict__ qry) {
    __shared__ float sbuf[16];
    int row = blockIdx.x;
    const float* src;
    __nv_bfloat16 *dh, *dp;
    if (row < SROWS) {
        src = sup + (size_t)row * CF;
        dh = g_Shi + (size_t)row * CF; dp = g_Sps + (size_t)row * CF;
    } else {
        int r = row - SROWS;
        src = qry + (size_t)r * CF;
        dh = g_Thi + (size_t)r * CF; dp = g_Tps + (size_t)r * CF;
    }
    int tid = threadIdx.x, lane = tid & 31, wid = tid >> 5;

    float4 v = ((const float4*)src)[tid];
    float s1 = v.x + v.y + v.z + v.w;
    float s2 = v.x*v.x + v.y*v.y + v.z*v.z + v.w*v.w;
#pragma unroll
    for (int o = 16; o > 0; o >>= 1) {
        s1 += __shfl_down_sync(0xffffffffu, s1, o);
        s2 += __shfl_down_sync(0xffffffffu, s2, o);
    }
    if (lane == 0) { sbuf[wid] = s1; sbuf[8 + wid] = s2; }
    __syncthreads();
    if (tid == 0) {
        float t1 = 0.f, t2 = 0.f;
        for (int w = 0; w < 5; w++) { t1 += sbuf[w]; t2 += sbuf[8 + w]; }
        sbuf[6] = t1; sbuf[7] = t2;
    }
    __syncthreads();
    float mean = sbuf[6] * (1.0f / CF);
    float ss = sbuf[7] - sbuf[6] * mean;   // sum x^2 - n*mean^2
    float inv = rsqrtf(ss + 1e-12f);

    float vv[4] = {(v.x - mean) * inv, (v.y - mean) * inv,
                   (v.z - mean) * inv, (v.w - mean) * inv};
    union { __nv_bfloat16 b[4]; uint2 u; } ph, pp;
#pragma unroll
    for (int k = 0; k < 4; k++) {
        float h = __bfloat162float(__float2bfloat16(vv[k]));
        ph.b[k] = __float2bfloat16(h);
        float P = __bfloat162float(__float2bfloat16(h + 256.0f * (vv[k] - h)));
        pp.b[k] = __float2bfloat16(P * 0.0625f);   // exact exponent shift
    }
    *reinterpret_cast<uint2*>(dh + tid * 4) = ph.u;
    *reinterpret_cast<uint2*>(dp + tid * 4) = pp.u;
}

// ---------------------------------------------------------------------------
// cross Gram: CTA tile 128x128; 8 warps 4x2, warp tile 32x64; cp.async 2-stage
#define X_STAGE 40960              // 4 arrays * 128*80
#define X_SMEM  (2*X_STAGE)        // 81920

__global__ __launch_bounds__(256, 2) void cross_mma() {
    extern __shared__ char smem[];
    __shared__ float tab[16];
    uint32_t sb = smem_u32(smem);
    int tid = threadIdx.x, lane = tid & 31, wid = tid >> 5;
    int wm = wid >> 1, wn = wid & 1;
    int gid = lane >> 2, tig = lane & 3;

    int bx = blockIdx.x;
    int nt_t = bx % 15;
    int mt_t = (bx / 15) % 6;
    int b    = bx / 90;

    int aValid = 650 - mt_t * 128; if (aValid > 128) aValid = 128;
    int bValid = 1875 - nt_t * 128; if (bValid > 128) bValid = 128;
    const char* A0 = (const char*)(g_Shi + ((size_t)b * 650 + mt_t * 128) * CF);
    const char* A1 = (const char*)(g_Sps + ((size_t)b * 650 + mt_t * 128) * CF);
    const char* B0 = (const char*)(g_Thi + ((size_t)b * 1875 + nt_t * 128) * CF);
    const char* B1 = (const char*)(g_Tps + ((size_t)b * 1875 + nt_t * 128) * CF);

    if (tid < 16) tab[tid] = 0.f;

    float acc[2][8][4];
#pragma unroll
    for (int i = 0; i < 2; i++)
#pragma unroll
        for (int j = 0; j < 8; j++)
#pragma unroll
            for (int k = 0; k < 4; k++) acc[i][j][k] = 0.f;

    int lrow = lane & 15, lcol = (lane >> 4) << 4;

    // fill(stage, chunk)
    auto fill = [&](int stage, int c) {
#pragma unroll
        for (int it = 0; it < 8; it++) {
            int idx = tid + it * 256;          // 0..2047
            int arr = idx >> 9;                // 0:Ahi 1:Aps 2:Bhi 3:Bps
            int rs  = idx & 511;
            int row = rs >> 2, seg = rs & 3;
            const char* base = (arr == 0) ? A0 : (arr == 1) ? A1
                             : (arr == 2) ? B0 : B1;
            int valid = (arr < 2) ? aValid : bValid;
            cp16(sb + stage * X_STAGE + arr * 10240 + row * RB + seg * 16,
                 base + (size_t)row * ROWB + c * 64 + seg * 16,
                 row < valid ? 16 : 0);
        }
        CP_COMMIT();
    };

    fill(0, 0);
    for (int c = 0; c < CH; c++) {
        if (c + 1 < CH) { fill((c + 1) & 1, c + 1); CP_WAIT1(); }
        else           { CP_WAIT0(); }
        __syncthreads();
        uint32_t base = sb + (c & 1) * X_STAGE;
#pragma unroll
        for (int ks = 0; ks < 2; ks++) {
            uint32_t ahi[2][4], aps[2][4];
#pragma unroll
            for (int mt = 0; mt < 2; mt++) {
                int ro = (wm * 32 + mt * 16 + lrow) * RB + ks * 32 + lcol;
                ldsm_x4(ahi[mt], base + ro);
                ldsm_x4(aps[mt], base + 10240 + ro);
            }
#pragma unroll
            for (int p = 0; p < 4; p++) {
                uint32_t bhi[4], bps[4];
                int ro = (wn * 64 + p * 16 + lrow) * RB + ks * 32 + lcol;
                ldsm_x4(bhi, base + 20480 + ro);
                ldsm_x4(bps, base + 30720 + ro);
#pragma unroll
                for (int mt = 0; mt < 2; mt++) {
                    mma4(acc[mt][p*2+0], ahi[mt], bhi[0], bhi[2]);
                    mma4(acc[mt][p*2+0], aps[mt], bps[0], bps[2]);
                    mma4(acc[mt][p*2+1], ahi[mt], bhi[1], bhi[3]);
                    mma4(acc[mt][p*2+1], aps[mt], bps[1], bps[3]);
                }
            }
        }
        __syncthreads();
    }

    // epilogue: multigauss + (w,q) bucket reduction
    int qb = nt_t * 128;
    int q_base = qb / 25;
    int w_base = (mt_t * 128) / 130;
#pragma unroll
    for (int mt = 0; mt < 2; mt++)
#pragma unroll
    for (int rh = 0; rh < 2; rh++) {
        int row = wm * 32 + mt * 16 + rh * 8 + gid;
        int gs = mt_t * 128 + row;
        if (gs < 650) {
            int wrel = gs / 130 - w_base;
            float run = 0.f;
            int qprev = (qb + wn * 64 + tig * 2) / 25;
#pragma unroll
            for (int nt = 0; nt < 8; nt++)
#pragma unroll
            for (int e = 0; e < 2; e++) {
                int gt = qb + wn * 64 + nt * 8 + tig * 2 + e;
                int q = gt / 25;
                if (q != qprev) {
                    atomicAdd(&tab[wrel * 8 + (qprev - q_base)], run);
                    run = 0.f; qprev = q;
                }
                if (gt < 1875) run += multigauss_acc(acc[mt][nt][rh * 2 + e]);
            }
            atomicAdd(&tab[wrel * 8 + (qprev - q_base)], run);
        }
    }
    __syncthreads();
    if (tid < 16) {
        float v = tab[tid];
        if (v != 0.f) {
            int q = q_base + (tid & 7);
            int w = w_base + (tid >> 3);
            if (q < NQQ && w < NWAY)
                atomicAdd(&g_qs_sum[(b * NQQ + q) * NWAY + w], v);
        }
    }
}

// ---------------------------------------------------------------------------
// query self Gram: CTA per (b, 5-q group); 5 warps, warp w -> diag block w
#define QROWS 132
#define Q_STAGE (2*QROWS*RB)       // hi+ps = 21120
#define Q_SMEM  (2*Q_STAGE)        // 42240

__global__ __launch_bounds__(160) void kqq_mma() {
    extern __shared__ char smem[];
    uint32_t sb = smem_u32(smem);
    int tid = threadIdx.x, lane = tid & 31, wid = tid >> 5;
    int gid = lane >> 2, tig = lane & 3;
    int b = blockIdx.x / 15, qg = blockIdx.x % 15;

    const char* H = (const char*)(g_Thi + ((size_t)b * 1875 + qg * 125) * CF);
    const char* P = (const char*)(g_Tps + ((size_t)b * 1875 + qg * 125) * CF);

    // pre-zero pad rows 125..131 in both arrays, both stages
    for (int idx = tid; idx < 4 * 7 * 5; idx += 160) {   // 4 bufs * 7 rows * 5 u4
        int buf = idx / 35, rr = (idx % 35) / 5, sg = idx % 5;
        int st = buf >> 1, arr = buf & 1;
        *(uint4*)(smem + st * Q_STAGE + arr * (QROWS*RB) + (125 + rr) * RB + sg * 16)
            = make_uint4(0,0,0,0);
    }
    __syncthreads();

    float acc[2][4][4];
#pragma unroll
    for (int i = 0; i < 2; i++)
#pragma unroll
        for (int j = 0; j < 4; j++)
#pragma unroll
            for (int k = 0; k < 4; k++) acc[i][j][k] = 0.f;

    int lrow = lane & 15, lcol = (lane >> 4) << 4;
    int rbase = wid * 25;

    auto fill = [&](int stage, int c) {
#pragma unroll
        for (int it = 0; it < 7; it++) {
            int idx = tid + it * 160;          // 0..1119 ; tasks 1000
            if (idx < 1000) {
                int arr = idx >= 500, rs = (idx >= 500) ? idx - 500 : idx;
                int row = rs >> 2, seg = rs & 3;
                const char* base = arr ? P : H;
                cp16(sb + stage * Q_STAGE + arr * (QROWS*RB) + row * RB + seg * 16,
                     base + (size_t)row * ROWB + c * 64 + seg * 16, 16);
            }
        }
        CP_COMMIT();
    };

    fill(0, 0);
    for (int c = 0; c < CH; c++) {
        if (c + 1 < CH) { fill((c + 1) & 1, c + 1); CP_WAIT1(); }
        else           { CP_WAIT0(); }
        __syncthreads();
        uint32_t base = sb + (c & 1) * Q_STAGE;
#pragma unroll
        for (int ks = 0; ks < 2; ks++) {
            uint32_t ahi[2][4], aps[2][4];
#pragma unroll
            for (int mt = 0; mt < 2; mt++) {
                int ro = (rbase + mt * 16 + lrow) * RB + ks * 32 + lcol;
                ldsm_x4(ahi[mt], base + ro);
                ldsm_x4(aps[mt], base + QROWS*RB + ro);
            }
#pragma unroll
            for (int p = 0; p < 2; p++) {
                uint32_t bhi[4], bps[4];
                int ro = (rbase + p * 16 + lrow) * RB + ks * 32 + lcol;
                ldsm_x4(bhi, base + ro);
                ldsm_x4(bps, base + QROWS*RB + ro);
#pragma unroll
                for (int mt = 0; mt < 2; mt++) {
                    mma4(acc[mt][p*2+0], ahi[mt], bhi[0], bhi[2]);
                    mma4(acc[mt][p*2+0], aps[mt], bps[0], bps[2]);
                    mma4(acc[mt][p*2+1], ahi[mt], bhi[1], bhi[3]);
                    mma4(acc[mt][p*2+1], aps[mt], bps[1], bps[3]);
                }
            }
        }
        __syncthreads();
    }

    float sum = 0.f;
#pragma unroll
    for (int mt = 0; mt < 2; mt++)
#pragma unroll
    for (int nt = 0; nt < 4; nt++)
#pragma unroll
    for (int rh = 0; rh < 2; rh++)
#pragma unroll
    for (int e = 0; e < 2; e++) {
        int row = mt * 16 + rh * 8 + gid;
        int col = nt * 8 + tig * 2 + e;
        if (row < NQ && col < NQ && row != col)
            sum += multigauss_acc(acc[mt][nt][rh * 2 + e]);
    }
#pragma unroll
    for (int o = 16; o > 0; o >>= 1) sum += __shfl_down_sync(0xffffffffu, sum, o);
    if (lane == 0)
        g_mmd_q[b * NQQ + qg * 5 + wid] = sum * (1.0f / (NQ * (NQ - 1)));
}

// ---------------------------------------------------------------------------
// support self Gram: CTA per (b,w); 9 warps 3x3, warp tile 48x48
#define SROWS_T 144
#define S_STAGE (2*SROWS_T*RB)     // 23040
#define S_SMEM  (2*S_STAGE)        // 46080

__global__ __launch_bounds__(288) void kss_mma() {
    extern __shared__ char smem[];
    __shared__ float red[9];
    uint32_t sb = smem_u32(smem);
    int tid = threadIdx.x, lane = tid & 31, wid = tid >> 5;
    int wm = wid / 3, wn = wid % 3;
    int gid = lane >> 2, tig = lane & 3;
    int b = blockIdx.x / NWAY, w = blockIdx.x % NWAY;

    const char* H = (const char*)(g_Shi + ((size_t)(b * NWAY + w) * NS) * CF);
    const char* P = (const char*)(g_Sps + ((size_t)(b * NWAY + w) * NS) * CF);

    // pre-zero pad rows 130..143
    for (int idx = tid; idx < 4 * 14 * 5; idx += 288) {
        int buf = idx / 70, rr = (idx % 70) / 5, sg = idx % 5;
        int st = buf >> 1, arr = buf & 1;
        *(uint4*)(smem + st * S_STAGE + arr * (SROWS_T*RB) + (130 + rr) * RB + sg * 16)
            = make_uint4(0,0,0,0);
    }
    __syncthreads();

    float acc[3][6][4];
#pragma unroll
    for (int i = 0; i < 3; i++)
#pragma unroll
        for (int j = 0; j < 6; j++)
#pragma unroll
            for (int k = 0; k < 4; k++) acc[i][j][k] = 0.f;

    int lrow = lane & 15, lcol = (lane >> 4) << 4;

    auto fill = [&](int stage, int c) {
#pragma unroll
        for (int it = 0; it < 4; it++) {
            int idx = tid + it * 288;          // tasks 1040
            if (idx < 1040) {
                int arr = idx >= 520, rs = arr ? idx - 520 : idx;
                int row = rs >> 2, seg = rs & 3;
                const char* base = arr ? P : H;
                cp16(sb + stage * S_STAGE + arr * (SROWS_T*RB) + row * RB + seg * 16,
                     base + (size_t)row * ROWB + c * 64 + seg * 16, 16);
            }
        }
        CP_COMMIT();
    };

    fill(0, 0);
    for (int c = 0; c < CH; c++) {
        if (c + 1 < CH) { fill((c + 1) & 1, c + 1); CP_WAIT1(); }
        else           { CP_WAIT0(); }
        __syncthreads();
        uint32_t base = sb + (c & 1) * S_STAGE;
#pragma unroll
        for (int ks = 0; ks < 2; ks++) {
            uint32_t ahi[3][4], aps[3][4];
#pragma unroll
            for (int mt = 0; mt < 3; mt++) {
                int ro = (wm * 48 + mt * 16 + lrow) * RB + ks * 32 + lcol;
                ldsm_x4(ahi[mt], base + ro);
                ldsm_x4(aps[mt], base + SROWS_T*RB + ro);
            }
#pragma unroll
            for (int p = 0; p < 3; p++) {
                uint32_t bhi[4], bps[4];
                int ro = (wn * 48 + p * 16 + lrow) * RB + ks * 32 + lcol;
                ldsm_x4(bhi, base + ro);
                ldsm_x4(bps, base + SROWS_T*RB + ro);
#pragma unroll
                for (int mt = 0; mt < 3; mt++) {
                    mma4(acc[mt][p*2+0], ahi[mt], bhi[0], bhi[2]);
                    mma4(acc[mt][p*2+0], aps[mt], bps[0], bps[2]);
                    mma4(acc[mt][p*2+1], ahi[mt], bhi[1], bhi[3]);
                    mma4(acc[mt][p*2+1], aps[mt], bps[1], bps[3]);
                }
            }
        }
        __syncthreads();
    }

    float sum = 0.f;
#pragma unroll
    for (int mt = 0; mt < 3; mt++)
#pragma unroll
    for (int nt = 0; nt < 6; nt++)
#pragma unroll
    for (int rh = 0; rh < 2; rh++)
#pragma unroll
    for (int e = 0; e < 2; e++) {
        int row = wm * 48 + mt * 16 + rh * 8 + gid;
        int col = wn * 48 + nt * 8 + tig * 2 + e;
        if (row < NS && col < NS && row != col)
            sum += multigauss_acc(acc[mt][nt][rh * 2 + e]);
    }
#pragma unroll
    for (int o = 16; o > 0; o >>= 1) sum += __shfl_down_sync(0xffffffffu, sum, o);
    if (lane == 0) red[wid] = sum;
    __syncthreads();
    if (tid == 0) {
        float t = 0.f;
        for (int i = 0; i < 9; i++) t += red[i];
        g_ss_sum[b * NWAY + w] = t;
    }
}

// ---------------------------------------------------------------------------
__global__ void combine_kernel(float* __restrict__ out) {
    int idx = blockIdx.x * blockDim.x + threadIdx.x;
    if (idx >= NB * NQQ * NWAY) return;
    int w = idx % NWAY;
    int bq = idx / NWAY;
    int b = bq / NQQ;
    out[idx] = g_ss_sum[b * NWAY + w] * (1.0f / (NS * (NS - 1)))
             + g_mmd_q[bq]
             - 2.0f * g_qs_sum[idx] * (1.0f / (NS * NQ));
}

// ---------------------------------------------------------------------------
extern "C" void kernel_launch(void* const* d_in, const int* in_sizes, int n_in,
                              void* d_out, int out_size) {
    const float* sup = (const float*)d_in[0];
    const float* qry = (const float*)d_in[1];
    float* out = (float*)d_out;
    (void)in_sizes; (void)n_in; (void)out_size;

    cudaFuncSetAttribute(cross_mma, cudaFuncAttributeMaxDynamicSharedMemorySize, X_SMEM);
    cudaFuncSetAttribute(kqq_mma,  cudaFuncAttributeMaxDynamicSharedMemorySize, Q_SMEM);
    cudaFuncSetAttribute(kss_mma,  cudaFuncAttributeMaxDynamicSharedMemorySize, S_SMEM);

    zero_kernel<<<24, 256>>>();
    norm_kernel<<<SROWS + TROWS, 160>>>(sup, qry);
    kss_mma<<<NB * NWAY, 288, S_SMEM>>>();
    kqq_mma<<<NB * 15, 160, Q_SMEM>>>();
    cross_mma<<<NB * 6 * 15, 256, X_SMEM>>>();
    combine_kernel<<<(NB * NQQ * NWAY + 127) / 128, 128>>>(out);
}